// round 5
// baseline (speedup 1.0000x reference)
#include <cuda_runtime.h>
#include <cfloat>

// Guided directional max pool (running cummax along W of x * guide).
// Shapes: x [B=8, C=256, H=128, W=128] fp32, guide [B,1,H,W] fp32.
// One warp per (b,c,h) row. Lane l owns elements [4l, 4l+4).
// Coalesced float4 loads, in-lane sequential cummax, warp shfl max-scan.

#define B_ 8
#define C_ 256
#define H_ 128
#define W_ 128

__global__ __launch_bounds__(256, 8)
void i5pool_kernel(const float* __restrict__ x,
                   const float* __restrict__ guide,
                   float* __restrict__ out)
{
    const int warp_in_block = threadIdx.x >> 5;
    const int lane          = threadIdx.x & 31;
    const long long row     = (long long)blockIdx.x * 8 + warp_in_block; // (b*C + c)*H + h

    // row -> guide row index: b*H + h
    const int bc = (int)(row / H_);       // b*C + c
    const int h  = (int)(row % H_);
    const int b  = bc / C_;

    const float4* xrow = reinterpret_cast<const float4*>(x + row * W_);
    const float4* grow = reinterpret_cast<const float4*>(guide + ((long long)b * H_ + h) * W_);
    float4*       orow = reinterpret_cast<float4*>(out + row * W_);

    float4 xv = xrow[lane];
    float4 gv = grow[lane];   // L2-resident after first c for this (b,h)

    // gated values
    float4 v;
    v.x = xv.x * gv.x;
    v.y = xv.y * gv.y;
    v.z = xv.z * gv.z;
    v.w = xv.w * gv.w;

    // in-lane inclusive cummax over the 4 owned elements
    v.y = fmaxf(v.y, v.x);
    v.z = fmaxf(v.z, v.y);
    v.w = fmaxf(v.w, v.z);

    // warp inclusive max-scan on lane totals (v.w)
    float total = v.w;
    #pragma unroll
    for (int off = 1; off < 32; off <<= 1) {
        float t = __shfl_up_sync(0xFFFFFFFFu, total, off);
        if (lane >= off) total = fmaxf(total, t);
    }
    // exclusive prefix for this lane
    float prefix = __shfl_up_sync(0xFFFFFFFFu, total, 1);
    if (lane == 0) prefix = -FLT_MAX;

    v.x = fmaxf(v.x, prefix);
    v.y = fmaxf(v.y, prefix);
    v.z = fmaxf(v.z, prefix);
    v.w = fmaxf(v.w, prefix);

    orow[lane] = v;
}

extern "C" void kernel_launch(void* const* d_in, const int* in_sizes, int n_in,
                              void* d_out, int out_size)
{
    const float* x     = (const float*)d_in[0];
    const float* guide = (const float*)d_in[1];
    float*       out   = (float*)d_out;

    // rows = B*C*H = 262144; 8 warps (one row each) per 256-thread block
    const int rows   = B_ * C_ * H_;
    const int blocks = rows / 8;   // 32768
    i5pool_kernel<<<blocks, 256>>>(x, guide, out);
}

// round 7
// speedup vs baseline: 1.0252x; 1.0252x over previous
#include <cuda_runtime.h>
#include <cfloat>

// Guided directional max pool: out[...,t] = max_{j<=t} x[...,j]*guide[b,0,h,j]
// x [8,256,128,128] fp32, guide [8,1,128,128] fp32.
//
// One warp per (b, c-pair, h): processes rows (b,c,h) and (b,c+1,h), which
// share the SAME guide row -> one guide load serves two rows. Lane l owns
// elements [4l,4l+4) of each row (float4, fully coalesced). Two independent
// shfl max-scans interleaved to overlap the shuffle dependency chains.
// x is read-once -> __ldcs (evict-first); out -> __stcs; guide cached normally.

#define B_ 8
#define C_ 256
#define H_ 128
#define W_ 128

__global__ __launch_bounds__(256, 8)
void i5pool_kernel(const float4* __restrict__ x,
                   const float4* __restrict__ guide,
                   float4* __restrict__ out)
{
    const unsigned lane = threadIdx.x & 31u;
    // global warp id: one warp per row-pair, 131072 total
    const unsigned w = (blockIdx.x << 3) + (threadIdx.x >> 5);

    const unsigned h     = w & (H_ - 1u);       // h
    const unsigned t     = w >> 7;              // b*(C/2) + cpair
    const unsigned cpair = t & (C_ / 2 - 1u);   // c/2
    const unsigned b     = t >> 7;              // b  (C/2 == 128)

    // row index in units of W floats; addresses below in float4 (W/4 = 32)
    const unsigned row0 = (b * C_ + cpair * 2u) * H_ + h;   // (b, 2*cpair, h)
    const unsigned row1 = row0 + H_;                        // (b, 2*cpair+1, h)
    const unsigned grow = b * H_ + h;

    // issue all three 128-bit loads before any dependent work (MLP = 3)
    float4 xv0 = __ldcs(&x[row0 * (W_ / 4) + lane]);
    float4 xv1 = __ldcs(&x[row1 * (W_ / 4) + lane]);
    float4 gv  = guide[grow * (W_ / 4) + lane];

    // gate
    float4 v0, v1;
    v0.x = xv0.x * gv.x;  v1.x = xv1.x * gv.x;
    v0.y = xv0.y * gv.y;  v1.y = xv1.y * gv.y;
    v0.z = xv0.z * gv.z;  v1.z = xv1.z * gv.z;
    v0.w = xv0.w * gv.w;  v1.w = xv1.w * gv.w;

    // in-lane inclusive cummax (two independent chains)
    v0.y = fmaxf(v0.y, v0.x);   v1.y = fmaxf(v1.y, v1.x);
    v0.z = fmaxf(v0.z, v0.y);   v1.z = fmaxf(v1.z, v1.y);
    v0.w = fmaxf(v0.w, v0.z);   v1.w = fmaxf(v1.w, v1.z);

    // warp inclusive max-scan on lane totals, both rows interleaved
    float t0 = v0.w, t1 = v1.w;
    #pragma unroll
    for (int off = 1; off < 32; off <<= 1) {
        float a0 = __shfl_up_sync(0xFFFFFFFFu, t0, off);
        float a1 = __shfl_up_sync(0xFFFFFFFFu, t1, off);
        if (lane >= (unsigned)off) { t0 = fmaxf(t0, a0); t1 = fmaxf(t1, a1); }
    }
    float p0 = __shfl_up_sync(0xFFFFFFFFu, t0, 1);
    float p1 = __shfl_up_sync(0xFFFFFFFFu, t1, 1);
    if (lane == 0u) { p0 = -FLT_MAX; p1 = -FLT_MAX; }

    v0.x = fmaxf(v0.x, p0);  v1.x = fmaxf(v1.x, p1);
    v0.y = fmaxf(v0.y, p0);  v1.y = fmaxf(v1.y, p1);
    v0.z = fmaxf(v0.z, p0);  v1.z = fmaxf(v1.z, p1);
    v0.w = fmaxf(v0.w, p0);  v1.w = fmaxf(v1.w, p1);

    __stcs(&out[row0 * (W_ / 4) + lane], v0);
    __stcs(&out[row1 * (W_ / 4) + lane], v1);
}

extern "C" void kernel_launch(void* const* d_in, const int* in_sizes, int n_in,
                              void* d_out, int out_size)
{
    const float4* x     = (const float4*)d_in[0];
    const float4* guide = (const float4*)d_in[1];
    float4*       out   = (float4*)d_out;

    // 131072 row-pairs, 8 warps per 256-thread block -> 16384 blocks
    const int pairs  = (B_ * C_ * H_) / 2;
    const int blocks = pairs / 8;
    i5pool_kernel<<<blocks, 256>>>(x, guide, out);
}

// round 10
// speedup vs baseline: 1.0572x; 1.0312x over previous
#include <cuda_runtime.h>
#include <cfloat>

// Guided directional max pool: out[...,t] = max_{j<=t} x[...,j]*guide[b,0,h,j]
// x [8,256,128,128] fp32, guide [8,1,128,128] fp32.
//
// One warp per (b, c-quad, h): processes rows (b,4q..4q+3,h), which all share
// the SAME guide row -> one guide load serves four rows (MLP=5 outstanding
// LDG.128 per thread). Lane l owns elements [4l,4l+4) of each row (float4,
// fully coalesced). Four independent shfl max-scans interleaved to overlap
// the shuffle dependency chains. x read-once -> __ldcs; out -> __stcs.

#define B_ 8
#define C_ 256
#define H_ 128
#define W_ 128

__global__ __launch_bounds__(256, 6)
void i5pool_kernel(const float4* __restrict__ x,
                   const float4* __restrict__ guide,
                   float4* __restrict__ out)
{
    const unsigned lane = threadIdx.x & 31u;
    // global warp id: one warp per row-quad, 65536 total
    const unsigned w = (blockIdx.x << 3) + (threadIdx.x >> 5);

    const unsigned h  = w & (H_ - 1u);        // h
    const unsigned t  = w >> 7;               // b*(C/4) + cq
    const unsigned cq = t & (C_ / 4 - 1u);    // c/4   (C/4 == 64)
    const unsigned b  = t >> 6;               // b

    // row indices (units of W floats); addresses below in float4 (W/4 = 32)
    const unsigned row0 = (b * C_ + cq * 4u) * H_ + h;
    const unsigned grow = b * H_ + h;

    // issue all five 128-bit loads before any dependent work (MLP = 5)
    float4 xv0 = __ldcs(&x[(row0          ) * (W_ / 4) + lane]);
    float4 xv1 = __ldcs(&x[(row0 +     H_ ) * (W_ / 4) + lane]);
    float4 xv2 = __ldcs(&x[(row0 + 2u * H_) * (W_ / 4) + lane]);
    float4 xv3 = __ldcs(&x[(row0 + 3u * H_) * (W_ / 4) + lane]);
    float4 gv  = guide[grow * (W_ / 4) + lane];

    // gate
    float4 v0, v1, v2, v3;
    v0.x = xv0.x * gv.x; v1.x = xv1.x * gv.x; v2.x = xv2.x * gv.x; v3.x = xv3.x * gv.x;
    v0.y = xv0.y * gv.y; v1.y = xv1.y * gv.y; v2.y = xv2.y * gv.y; v3.y = xv3.y * gv.y;
    v0.z = xv0.z * gv.z; v1.z = xv1.z * gv.z; v2.z = xv2.z * gv.z; v3.z = xv3.z * gv.z;
    v0.w = xv0.w * gv.w; v1.w = xv1.w * gv.w; v2.w = xv2.w * gv.w; v3.w = xv3.w * gv.w;

    // in-lane inclusive cummax (four independent chains)
    v0.y = fmaxf(v0.y, v0.x); v1.y = fmaxf(v1.y, v1.x); v2.y = fmaxf(v2.y, v2.x); v3.y = fmaxf(v3.y, v3.x);
    v0.z = fmaxf(v0.z, v0.y); v1.z = fmaxf(v1.z, v1.y); v2.z = fmaxf(v2.z, v2.y); v3.z = fmaxf(v3.z, v3.y);
    v0.w = fmaxf(v0.w, v0.z); v1.w = fmaxf(v1.w, v1.z); v2.w = fmaxf(v2.w, v2.z); v3.w = fmaxf(v3.w, v3.z);

    // warp inclusive max-scan on lane totals, four rows interleaved
    float t0 = v0.w, t1 = v1.w, t2 = v2.w, t3 = v3.w;
    #pragma unroll
    for (int off = 1; off < 32; off <<= 1) {
        float a0 = __shfl_up_sync(0xFFFFFFFFu, t0, off);
        float a1 = __shfl_up_sync(0xFFFFFFFFu, t1, off);
        float a2 = __shfl_up_sync(0xFFFFFFFFu, t2, off);
        float a3 = __shfl_up_sync(0xFFFFFFFFu, t3, off);
        if (lane >= (unsigned)off) {
            t0 = fmaxf(t0, a0); t1 = fmaxf(t1, a1);
            t2 = fmaxf(t2, a2); t3 = fmaxf(t3, a3);
        }
    }
    float p0 = __shfl_up_sync(0xFFFFFFFFu, t0, 1);
    float p1 = __shfl_up_sync(0xFFFFFFFFu, t1, 1);
    float p2 = __shfl_up_sync(0xFFFFFFFFu, t2, 1);
    float p3 = __shfl_up_sync(0xFFFFFFFFu, t3, 1);
    if (lane == 0u) { p0 = -FLT_MAX; p1 = -FLT_MAX; p2 = -FLT_MAX; p3 = -FLT_MAX; }

    v0.x = fmaxf(v0.x, p0); v1.x = fmaxf(v1.x, p1); v2.x = fmaxf(v2.x, p2); v3.x = fmaxf(v3.x, p3);
    v0.y = fmaxf(v0.y, p0); v1.y = fmaxf(v1.y, p1); v2.y = fmaxf(v2.y, p2); v3.y = fmaxf(v3.y, p3);
    v0.z = fmaxf(v0.z, p0); v1.z = fmaxf(v1.z, p1); v2.z = fmaxf(v2.z, p2); v3.z = fmaxf(v3.z, p3);
    v0.w = fmaxf(v0.w, p0); v1.w = fmaxf(v1.w, p1); v2.w = fmaxf(v2.w, p2); v3.w = fmaxf(v3.w, p3);

    __stcs(&out[(row0          ) * (W_ / 4) + lane], v0);
    __stcs(&out[(row0 +     H_ ) * (W_ / 4) + lane], v1);
    __stcs(&out[(row0 + 2u * H_) * (W_ / 4) + lane], v2);
    __stcs(&out[(row0 + 3u * H_) * (W_ / 4) + lane], v3);
}

extern "C" void kernel_launch(void* const* d_in, const int* in_sizes, int n_in,
                              void* d_out, int out_size)
{
    const float4* x     = (const float4*)d_in[0];
    const float4* guide = (const float4*)d_in[1];
    float4*       out   = (float4*)d_out;

    // 65536 row-quads, 8 warps per 256-thread block -> 8192 blocks
    const int quads  = (B_ * C_ * H_) / 4;
    const int blocks = quads / 8;
    i5pool_kernel<<<blocks, 256>>>(x, guide, out);
}